// round 9
// baseline (speedup 1.0000x reference)
#include <cuda_runtime.h>
#include <cuda_bf16.h>
#include <cuda_fp16.h>
#include <math.h>
#include <stdint.h>

// ---------------------------------------------------------------------------
// Relational graph attention, L2-resident grouped formulation.
//   Relations processed in 4 groups of 4. Per group:
//     Y[r] = ego @ W[r]  (bf16 HMMA, fp16 store)  -> 51MB slice, stays in L2
//     edge pass over edges pre-binned to this group consumes Y from L2.
//   out[n] = sum_e exp(s_e) * ego[t_e] / (den[n] * max(cnt[n],1))
// ---------------------------------------------------------------------------

#define N_CAP   131072
#define YROWS   102400               // >= N, multiple of 128
#define E_CAP   1310720
#define NGRP    4
#define RPG     4                    // relations per group

__device__ __half g_Yh[(size_t)RPG * YROWS * 64u];   // [4, N, 64] fp16 (51MB)
__device__ __half g_egoh[(size_t)N_CAP * 64];        // fp16 ego (edge tails)
__device__ __nv_bfloat16 g_egob[(size_t)N_CAP * 64]; // bf16 ego (GEMM A)
__device__ float2 g_dencnt[N_CAP];                   // (den, cnt) per head
__device__ int4  g_eperm[(size_t)NGRP * E_CAP];      // binned packed edges
__device__ int   g_bincnt[NGRP];

// pre-transposed W (row n, col k), padded row stride AS, bf16
#define AS 72
__device__ __nv_bfloat16 g_Wt[16 * 64 * AS];

__device__ __forceinline__ uint32_t smem_u32(const void* p) {
    uint32_t a;
    asm("{ .reg .u64 t; cvta.to.shared.u64 t, %1; cvt.u32.u64 %0, t; }"
        : "=r"(a) : "l"(p));
    return a;
}
__device__ __forceinline__ void ldm_x4(uint32_t* r, uint32_t addr) {
    asm volatile("ldmatrix.sync.aligned.m8n8.x4.shared.b16 {%0,%1,%2,%3}, [%4];"
                 : "=r"(r[0]), "=r"(r[1]), "=r"(r[2]), "=r"(r[3]) : "r"(addr));
}
__device__ __forceinline__ void mma_bf16(float* c, const uint32_t* a,
                                         uint32_t b0, uint32_t b1) {
    asm volatile(
        "mma.sync.aligned.m16n8k16.row.col.f32.bf16.bf16.f32 "
        "{%0,%1,%2,%3}, {%4,%5,%6,%7}, {%8,%9}, {%0,%1,%2,%3};"
        : "+f"(c[0]), "+f"(c[1]), "+f"(c[2]), "+f"(c[3])
        : "r"(a[0]), "r"(a[1]), "r"(a[2]), "r"(a[3]), "r"(b0), "r"(b1));
}

// smem layout (bytes): A = 128 rows x AS halves (18432), then B (9216)
#define A_OFF   0
#define B_OFF   18432
#define SMEM_SZ (18432 + 9216 + 128)

// ============================ kernels ======================================

// ---- zero out/dencnt/bincnt + fp16 & bf16 ego mirrors; blocks 0..15 prep W
__global__ void zero_kernel(float4* __restrict__ out4,
                            const float4* __restrict__ ego4,
                            const float* __restrict__ Wg,
                            int n_out4, int n_dc4)
{
    int i = blockIdx.x * blockDim.x + threadIdx.x;
    if (i < n_out4) {
        out4[i] = make_float4(0.f, 0.f, 0.f, 0.f);
        float4 v = ego4[i];
        __half2 h0 = __floats2half2_rn(v.x, v.y);
        __half2 h1 = __floats2half2_rn(v.z, v.w);
        *(uint2*)(g_egoh + (size_t)i * 4) =
            make_uint2(*(uint32_t*)&h0, *(uint32_t*)&h1);
        __nv_bfloat162 b0 = __floats2bfloat162_rn(v.x, v.y);
        __nv_bfloat162 b1 = __floats2bfloat162_rn(v.z, v.w);
        *(uint2*)(g_egob + (size_t)i * 4) =
            make_uint2(*(uint32_t*)&b0, *(uint32_t*)&b1);
    }
    if (i < n_dc4) ((float4*)g_dencnt)[i] = make_float4(0.f, 0.f, 0.f, 0.f);
    if (i < NGRP) g_bincnt[i] = 0;

    if (blockIdx.x < 16) {           // W transpose to bf16, padded stride
        const int r = blockIdx.x;
        for (int idx = threadIdx.x; idx < 4096; idx += 256) {
            int k = idx >> 6, n = idx & 63;          // W[k][n], coalesced read
            float v = Wg[(size_t)r * 4096 + idx];
            g_Wt[r * 64 * AS + n * AS + k] = __float2bfloat16(v);
        }
    }
}

// ---- bin edges by relation group (warp-aggregated atomics) ----------------
__global__ __launch_bounds__(256) void bin_scatter(
    const int* __restrict__ heads, const int* __restrict__ tails,
    const int* __restrict__ etype, int E)
{
    int i = blockIdx.x * 256 + threadIdx.x;
    bool valid = i < E;
    unsigned active = __ballot_sync(0xffffffffu, valid);
    if (!valid) return;

    int h = heads[i], t = tails[i], r = etype[i];
    int b = r >> 2;
    int lane = threadIdx.x & 31;
    int pos = 0;
    #pragma unroll
    for (int bb = 0; bb < NGRP; bb++) {
        unsigned m = __ballot_sync(active, b == bb);
        if (b == bb) {
            int leader = __ffs(m) - 1;
            int base = 0;
            if (lane == leader) base = atomicAdd(&g_bincnt[bb], __popc(m));
            base = __shfl_sync(m, base, leader);
            pos = base + __popc(m & ((1u << lane) - 1u));
        }
    }
    g_eperm[(size_t)b * E_CAP + pos] = make_int4(h, t, r, 0);
}

// ---- GEMM: Y[r-rbase] = ego @ W[r] for r in [rbase, rbase+4) --------------
__global__ __launch_bounds__(256) void gemm_transform(int rbase, int N)
{
    extern __shared__ __align__(16) char sm[];
    __nv_bfloat16* sh = (__nv_bfloat16*)sm;
    const uint32_t smb = smem_u32(sm);

    const int tid  = threadIdx.x;
    const int wid  = tid >> 5;
    const int lane = tid & 31;
    const int tile = blockIdx.x;
    const int rows = min(128, N - tile * 128);

    // --- stage A tile from bf16 mirror (pure vector copies) ----------------
    for (int i = tid; i < 128 * 8; i += 256) {       // 8 uint4 per row
        int row = i >> 3, q = i & 7;
        uint4 v = make_uint4(0u, 0u, 0u, 0u);
        if (row < rows)
            v = *(const uint4*)(g_egob + ((size_t)(tile * 128 + row)) * 64 + q * 8);
        *(uint4*)(sh + row * AS + q * 8) = v;
    }
    __syncthreads();

    // --- per-warp A fragment: 16 rows x K=64, loaded once ------------------
    const int m0   = wid * 16;
    const int frow = (lane & 7) + ((lane >> 3) & 1) * 8;
    const int fcol = (lane >> 4) * 8;
    uint32_t Af[4][4];
    #pragma unroll
    for (int kt = 0; kt < 4; kt++) {
        uint32_t off = (uint32_t)((m0 + frow) * AS + kt * 16 + fcol) * 2;
        ldm_x4(Af[kt], smb + A_OFF + off);
    }

    const int g  = lane >> 2;         // output row within 8-group
    const int tq = lane & 3;          // output col pair

    for (int rr = 0; rr < RPG; rr++) {
        const int r = rbase + rr;
        // stage B = pre-transposed W_r (pure vector copies)
        {
            const uint4* src = (const uint4*)(g_Wt + r * 64 * AS);
            uint4* dst = (uint4*)(sm + B_OFF);
            #pragma unroll
            for (int k = 0; k < 3; k++) {
                int i = tid + k * 256;
                if (i < 576) dst[i] = src[i];
            }
        }
        __syncthreads();

        float acc[8][4];
        #pragma unroll
        for (int i = 0; i < 8; i++)
            #pragma unroll
            for (int j = 0; j < 4; j++) acc[i][j] = 0.f;

        #pragma unroll
        for (int nt = 0; nt < 4; nt++) {
            #pragma unroll
            for (int kt = 0; kt < 4; kt++) {
                uint32_t boff = (uint32_t)((nt * 16 + frow) * AS + kt * 16 + fcol) * 2;
                uint32_t Bf[4];
                ldm_x4(Bf, smb + B_OFF + boff);
                mma_bf16(acc[2 * nt],     Af[kt], Bf[0], Bf[2]);
                mma_bf16(acc[2 * nt + 1], Af[kt], Bf[1], Bf[3]);
            }
        }

        // store Y slice as fp16 (half2 per (row, colpair))
        int row0  = m0 + g;
        uint32_t node0 = (uint32_t)(tile * 128 + row0);
        #pragma unroll
        for (int nt8 = 0; nt8 < 8; nt8++) {
            int col = nt8 * 8 + tq * 2;
            if (row0 < rows) {
                __half2 h = __floats2half2_rn(acc[nt8][0], acc[nt8][1]);
                *(uint32_t*)(g_Yh + ((uint32_t)rr * (uint32_t)N + node0) * 64u + col)
                    = *(uint32_t*)&h;
            }
            if (row0 + 8 < rows) {
                __half2 h = __floats2half2_rn(acc[nt8][2], acc[nt8][3]);
                *(uint32_t*)(g_Yh + ((uint32_t)rr * (uint32_t)N + node0 + 8u) * 64u + col)
                    = *(uint32_t*)&h;
            }
        }
        __syncthreads();   // B consumed before next relation restages
    }
}

// ---- edge pass over one bin: 8 edges/warp, grid-stride, fp16 gathers ------
__global__ __launch_bounds__(256) void edge_pass(
    float* __restrict__ out, int grp, int N)
{
    const int warp0 = (blockIdx.x * 256 + threadIdx.x) >> 5;
    const int lane  = threadIdx.x & 31;
    const int half  = lane >> 4;
    const int l2    = lane & 15;
    const unsigned hmask = 0xFFFFu << (half * 16);
    const int nwarps = gridDim.x * 8;

    const int cnt = g_bincnt[grp];
    const int4* perm = g_eperm + (size_t)grp * E_CAP;
    const uint32_t c8 = (uint32_t)(l2 * 4);

    for (int w = warp0; ; w += nwarps) {
        const int ebase = w * 8 + half * 4;
        if (ebase >= cnt) break;

        int4 ed[4];
        #pragma unroll
        for (int j = 0; j < 4; j++)
            ed[j] = perm[min(ebase + j, cnt - 1)];

        // issue all gathers (8 independent loads in flight)
        uint2 yv[4], tv[4];
        #pragma unroll
        for (int j = 0; j < 4; j++) {
            uint32_t rel = (uint32_t)(ed[j].z & 3);
            yv[j] = *(const uint2*)(g_Yh + (rel * (uint32_t)N + (uint32_t)ed[j].x) * 64u + c8);
            tv[j] = *(const uint2*)(g_egoh + (uint32_t)ed[j].y * 64u + c8);
        }

        float p[4], tf[4][4];
        #pragma unroll
        for (int j = 0; j < 4; j++) {
            float2 ya = __half22float2(*(__half2*)&yv[j].x);
            float2 yb = __half22float2(*(__half2*)&yv[j].y);
            float2 ta = __half22float2(*(__half2*)&tv[j].x);
            float2 tb = __half22float2(*(__half2*)&tv[j].y);
            tf[j][0] = ta.x; tf[j][1] = ta.y; tf[j][2] = tb.x; tf[j][3] = tb.y;
            p[j] = ya.x * ta.x + ya.y * ta.y + yb.x * tb.x + yb.y * tb.y;
        }
        #pragma unroll
        for (int o = 1; o < 16; o <<= 1) {
            #pragma unroll
            for (int j = 0; j < 4; j++)
                p[j] += __shfl_xor_sync(hmask, p[j], o);
        }

        float ex[4];
        #pragma unroll
        for (int j = 0; j < 4; j++) {
            float s = p[j] > 0.f ? p[j] : 0.01f * p[j];
            ex[j] = __expf(s);
        }

        #pragma unroll
        for (int j = 0; j < 4; j++) {
            if (ebase + j >= cnt) break;
            if (l2 == 0)
                asm volatile("red.global.add.v2.f32 [%0], {%1, %2};"
                             :: "l"(&g_dencnt[ed[j].x]), "f"(ex[j]), "f"(1.0f)
                             : "memory");
            float* op = out + (uint32_t)ed[j].x * 64u + c8;
            asm volatile("red.global.add.v4.f32 [%0], {%1, %2, %3, %4};"
                         :: "l"(op), "f"(ex[j] * tf[j][0]), "f"(ex[j] * tf[j][1]),
                            "f"(ex[j] * tf[j][2]), "f"(ex[j] * tf[j][3])
                         : "memory");
        }
    }
}

// ---- epilogue: divide by den * max(cnt,1), float4 per thread --------------
__global__ void pass3_mean(float4* __restrict__ out4, int N)
{
    int i = blockIdx.x * blockDim.x + threadIdx.x;    // one float4 (4 elems)
    if (i < N * 16) {
        float2 dc = g_dencnt[i >> 4];
        float s = (dc.y > 0.0f) ? __frcp_rn(dc.x * dc.y) : 0.0f;
        float4 v = out4[i];
        v.x *= s; v.y *= s; v.z *= s; v.w *= s;
        out4[i] = v;
    }
}

// ---------------------------------------------------------------------------
extern "C" void kernel_launch(void* const* d_in, const int* in_sizes, int n_in,
                              void* d_out, int out_size)
{
    const float* ego = (const float*)d_in[0];   // [N,64] f32
    const float* Wg  = (const float*)d_in[1];   // [16,64,64] f32
    const int*   ei  = (const int*)d_in[2];     // [2,E] i32
    const int*   et  = (const int*)d_in[3];     // [E] i32
    float* out = (float*)d_out;

    const int N = in_sizes[0] / 64;
    const int E = in_sizes[3];
    const int* heads = ei;
    const int* tails = ei + E;

    cudaFuncSetAttribute(gemm_transform,
                         cudaFuncAttributeMaxDynamicSharedMemorySize, SMEM_SZ);

    const int n_out4 = N * 16;                  // out as float4
    const int n_dc4  = (N * 2 + 3) / 4;         // dencnt as float4
    zero_kernel<<<(n_out4 + 255) / 256, 256>>>((float4*)out, (const float4*)ego,
                                               Wg, n_out4, n_dc4);

    bin_scatter<<<(E + 255) / 256, 256>>>(heads, tails, et, E);

    const int tiles = (N + 127) / 128;
    // edge grid sized for ~E/4 + 25% slack; grid-stride handles any skew
    const int ecover = E / NGRP + E / 16 + 64;
    const int edge_ctas = (ecover + 63) / 64;

    for (int g = 0; g < NGRP; g++) {
        gemm_transform<<<tiles, 256, SMEM_SZ>>>(g * RPG, N);
        edge_pass<<<edge_ctas, 256>>>(out, g, N);
    }

    pass3_mean<<<(n_out4 + 255) / 256, 256>>>((float4*)out, N);
}

// round 10
// speedup vs baseline: 1.6067x; 1.6067x over previous
#include <cuda_runtime.h>
#include <cuda_bf16.h>
#include <cuda_fp16.h>
#include <math.h>
#include <stdint.h>

// ---------------------------------------------------------------------------
// Aggregator: relational graph attention, tensor-core (warp mma.sync) version.
//   Y[r]     = ego @ W[r]            (bf16 HMMA, fp32 accumulate, fp16 store)
//   s_e      = leaky_relu( Y[et_e, h_e] . ego[t_e] )
//   out[n]   = sum_e exp(s_e) * ego[t_e]  /  ( den[n] * max(cnt[n],1) )
// GEMM grid is fully flattened: one CTA per (128-row tile, relation).
// ---------------------------------------------------------------------------

#define N_CAP   131072
#define YROWS   102400               // >= N, multiple of 128
__device__ __half g_Yh[16u * YROWS * 64u];           // [R, N, 64] fp16
__device__ __half g_egoh[(size_t)N_CAP * 64];        // fp16 ego (edge tails)
__device__ __nv_bfloat16 g_egob[(size_t)N_CAP * 64]; // bf16 ego (GEMM A)
__device__ float2 g_dencnt[N_CAP];                   // (den, cnt) per head

// pre-transposed W (row n, col k), padded row stride AS, bf16
#define AS 72
__device__ __nv_bfloat16 g_Wt[16 * 64 * AS];

__device__ __forceinline__ uint32_t smem_u32(const void* p) {
    uint32_t a;
    asm("{ .reg .u64 t; cvta.to.shared.u64 t, %1; cvt.u32.u64 %0, t; }"
        : "=r"(a) : "l"(p));
    return a;
}
__device__ __forceinline__ void ldm_x4(uint32_t* r, uint32_t addr) {
    asm volatile("ldmatrix.sync.aligned.m8n8.x4.shared.b16 {%0,%1,%2,%3}, [%4];"
                 : "=r"(r[0]), "=r"(r[1]), "=r"(r[2]), "=r"(r[3]) : "r"(addr));
}
__device__ __forceinline__ void mma_bf16(float* c, const uint32_t* a,
                                         uint32_t b0, uint32_t b1) {
    asm volatile(
        "mma.sync.aligned.m16n8k16.row.col.f32.bf16.bf16.f32 "
        "{%0,%1,%2,%3}, {%4,%5,%6,%7}, {%8,%9}, {%0,%1,%2,%3};"
        : "+f"(c[0]), "+f"(c[1]), "+f"(c[2]), "+f"(c[3])
        : "r"(a[0]), "r"(a[1]), "r"(a[2]), "r"(a[3]), "r"(b0), "r"(b1));
}

// smem layout (bytes): A = 128 rows x AS halves (18432), then B (9216)
#define A_OFF   0
#define B_OFF   18432
#define SMEM_SZ (18432 + 9216 + 128)

// ============================ kernels ======================================

// ---- zero out/dencnt + fp16 & bf16 ego mirrors; blocks 0..15 also prep W --
__global__ void zero_kernel(float4* __restrict__ out4,
                            const float4* __restrict__ ego4,
                            const float* __restrict__ Wg,
                            int n_out4, int n_dc4)
{
    int i = blockIdx.x * blockDim.x + threadIdx.x;
    if (i < n_out4) {
        out4[i] = make_float4(0.f, 0.f, 0.f, 0.f);
        float4 v = ego4[i];
        __half2 h0 = __floats2half2_rn(v.x, v.y);
        __half2 h1 = __floats2half2_rn(v.z, v.w);
        *(uint2*)(g_egoh + (size_t)i * 4) =
            make_uint2(*(uint32_t*)&h0, *(uint32_t*)&h1);
        __nv_bfloat162 b0 = __floats2bfloat162_rn(v.x, v.y);
        __nv_bfloat162 b1 = __floats2bfloat162_rn(v.z, v.w);
        *(uint2*)(g_egob + (size_t)i * 4) =
            make_uint2(*(uint32_t*)&b0, *(uint32_t*)&b1);
    }
    if (i < n_dc4) ((float4*)g_dencnt)[i] = make_float4(0.f, 0.f, 0.f, 0.f);

    if (blockIdx.x < 16) {           // W transpose to bf16, padded stride
        const int r = blockIdx.x;
        for (int idx = threadIdx.x; idx < 4096; idx += 256) {
            int k = idx >> 6, n = idx & 63;          // W[k][n], coalesced read
            float v = Wg[(size_t)r * 4096 + idx];
            g_Wt[r * 64 * AS + n * AS + k] = __float2bfloat16(v);
        }
    }
}

// ---- GEMM: one CTA per (tile, relation); no serial loop -------------------
__global__ __launch_bounds__(256) void gemm_transform(int N)
{
    extern __shared__ __align__(16) char sm[];
    __nv_bfloat16* sh = (__nv_bfloat16*)sm;
    const uint32_t smb = smem_u32(sm);

    const int tid  = threadIdx.x;
    const int wid  = tid >> 5;
    const int lane = tid & 31;
    const int r    = blockIdx.x & 15;        // relation (adjacent CTAs share tile)
    const int tile = blockIdx.x >> 4;
    const int rows = min(128, N - tile * 128);

    // --- stage A tile from bf16 mirror (vector copies, 4 uint4/thread) -----
    #pragma unroll
    for (int q = 0; q < 4; q++) {
        int i = tid + q * 256;               // 1024 uint4 total
        int row = i >> 3, seg = i & 7;
        uint4 v = make_uint4(0u, 0u, 0u, 0u);
        if (row < rows)
            v = *(const uint4*)(g_egob + ((size_t)(tile * 128 + row)) * 64 + seg * 8);
        *(uint4*)(sh + row * AS + seg * 8) = v;
    }
    // --- stage B = pre-transposed W_r (vector copies) ----------------------
    {
        const uint4* src = (const uint4*)(g_Wt + r * 64 * AS);
        uint4* dst = (uint4*)(sm + B_OFF);
        #pragma unroll
        for (int k = 0; k < 3; k++) {
            int i = tid + k * 256;
            if (i < 576) dst[i] = src[i];
        }
    }
    __syncthreads();                          // single barrier

    // --- fragments + MMA ----------------------------------------------------
    const int m0   = wid * 16;
    const int frow = (lane & 7) + ((lane >> 3) & 1) * 8;
    const int fcol = (lane >> 4) * 8;
    uint32_t Af[4][4];
    #pragma unroll
    for (int kt = 0; kt < 4; kt++) {
        uint32_t off = (uint32_t)((m0 + frow) * AS + kt * 16 + fcol) * 2;
        ldm_x4(Af[kt], smb + A_OFF + off);
    }

    float acc[8][4];
    #pragma unroll
    for (int i = 0; i < 8; i++)
        #pragma unroll
        for (int j = 0; j < 4; j++) acc[i][j] = 0.f;

    #pragma unroll
    for (int nt = 0; nt < 4; nt++) {
        #pragma unroll
        for (int kt = 0; kt < 4; kt++) {
            uint32_t boff = (uint32_t)((nt * 16 + frow) * AS + kt * 16 + fcol) * 2;
            uint32_t Bf[4];
            ldm_x4(Bf, smb + B_OFF + boff);
            mma_bf16(acc[2 * nt],     Af[kt], Bf[0], Bf[2]);
            mma_bf16(acc[2 * nt + 1], Af[kt], Bf[1], Bf[3]);
        }
    }

    // --- store Y tile as fp16 (half2 per (row, colpair)) -------------------
    const int g  = lane >> 2;
    const int tq = lane & 3;
    int row0  = m0 + g;
    uint32_t node0 = (uint32_t)(tile * 128 + row0);
    #pragma unroll
    for (int nt8 = 0; nt8 < 8; nt8++) {
        int col = nt8 * 8 + tq * 2;
        if (row0 < rows) {
            __half2 h = __floats2half2_rn(acc[nt8][0], acc[nt8][1]);
            *(uint32_t*)(g_Yh + ((uint32_t)r * (uint32_t)N + node0) * 64u + col)
                = *(uint32_t*)&h;
        }
        if (row0 + 8 < rows) {
            __half2 h = __floats2half2_rn(acc[nt8][2], acc[nt8][3]);
            *(uint32_t*)(g_Yh + ((uint32_t)r * (uint32_t)N + node0 + 8u) * 64u + col)
                = *(uint32_t*)&h;
        }
    }
}

// ---- fused edge pass: 8 edges/warp (4 per half), fp16 gathers -------------
__global__ __launch_bounds__(256) void edge_pass(
    const int*   __restrict__ heads,
    const int*   __restrict__ tails,
    const int*   __restrict__ etype,
    float*       __restrict__ out,
    int N, int E)
{
    const int warp = (blockIdx.x * 256 + threadIdx.x) >> 5;
    const int lane = threadIdx.x & 31;
    const int half = lane >> 4;
    const int l2   = lane & 15;
    const unsigned hmask = 0xFFFFu << (half * 16);

    const int ebase = warp * 8 + half * 4;     // this half-warp: 4 edges
    if (ebase >= E) return;

    int4 hh, tt, rr;
    if (ebase + 3 < E) {
        hh = *(const int4*)(heads + ebase);
        tt = *(const int4*)(tails + ebase);
        rr = *(const int4*)(etype + ebase);
    } else {
        int* hp = (int*)&hh; int* tp = (int*)&tt; int* rp = (int*)&rr;
        #pragma unroll
        for (int j = 0; j < 4; j++) {
            int e = min(ebase + j, E - 1);
            hp[j] = heads[e]; tp[j] = tails[e]; rp[j] = etype[e];
        }
    }
    const int* hp = (const int*)&hh;
    const int* tp = (const int*)&tt;
    const int* rp = (const int*)&rr;

    const uint32_t c8 = (uint32_t)(l2 * 4);

    // issue all gathers first (8 independent loads in flight)
    uint2 yv[4], tv[4];
    #pragma unroll
    for (int j = 0; j < 4; j++) {
        yv[j] = *(const uint2*)(g_Yh + ((uint32_t)rp[j] * (uint32_t)N + (uint32_t)hp[j]) * 64u + c8);
        tv[j] = *(const uint2*)(g_egoh + (uint32_t)tp[j] * 64u + c8);
    }

    float p[4];
    float tf[4][4];
    #pragma unroll
    for (int j = 0; j < 4; j++) {
        float2 ya = __half22float2(*(__half2*)&yv[j].x);
        float2 yb = __half22float2(*(__half2*)&yv[j].y);
        float2 ta = __half22float2(*(__half2*)&tv[j].x);
        float2 tb = __half22float2(*(__half2*)&tv[j].y);
        tf[j][0] = ta.x; tf[j][1] = ta.y; tf[j][2] = tb.x; tf[j][3] = tb.y;
        p[j] = ya.x * ta.x + ya.y * ta.y + yb.x * tb.x + yb.y * tb.y;
    }
    #pragma unroll
    for (int o = 1; o < 16; o <<= 1) {
        #pragma unroll
        for (int j = 0; j < 4; j++)
            p[j] += __shfl_xor_sync(hmask, p[j], o);
    }

    float ex[4];
    #pragma unroll
    for (int j = 0; j < 4; j++) {
        float s = p[j] > 0.f ? p[j] : 0.01f * p[j];
        ex[j] = __expf(s);
    }

    #pragma unroll
    for (int j = 0; j < 4; j++) {
        if (ebase + j >= E) break;
        if (l2 == 0)
            asm volatile("red.global.add.v2.f32 [%0], {%1, %2};"
                         :: "l"(&g_dencnt[hp[j]]), "f"(ex[j]), "f"(1.0f) : "memory");
        float* op = out + (uint32_t)hp[j] * 64u + c8;
        asm volatile("red.global.add.v4.f32 [%0], {%1, %2, %3, %4};"
                     :: "l"(op), "f"(ex[j] * tf[j][0]), "f"(ex[j] * tf[j][1]),
                        "f"(ex[j] * tf[j][2]), "f"(ex[j] * tf[j][3]) : "memory");
    }
}

// ---- epilogue: divide by den * max(cnt,1), float4 per thread --------------
__global__ void pass3_mean(float4* __restrict__ out4, int N)
{
    int i = blockIdx.x * blockDim.x + threadIdx.x;    // one float4 (4 elems)
    if (i < N * 16) {
        float2 dc = g_dencnt[i >> 4];
        float s = (dc.y > 0.0f) ? __frcp_rn(dc.x * dc.y) : 0.0f;
        float4 v = out4[i];
        v.x *= s; v.y *= s; v.z *= s; v.w *= s;
        out4[i] = v;
    }
}

// ---------------------------------------------------------------------------
extern "C" void kernel_launch(void* const* d_in, const int* in_sizes, int n_in,
                              void* d_out, int out_size)
{
    const float* ego = (const float*)d_in[0];   // [N,64] f32
    const float* Wg  = (const float*)d_in[1];   // [16,64,64] f32
    const int*   ei  = (const int*)d_in[2];     // [2,E] i32
    const int*   et  = (const int*)d_in[3];     // [E] i32
    float* out = (float*)d_out;

    const int N = in_sizes[0] / 64;
    const int E = in_sizes[3];
    const int* heads = ei;
    const int* tails = ei + E;

    cudaFuncSetAttribute(gemm_transform,
                         cudaFuncAttributeMaxDynamicSharedMemorySize, SMEM_SZ);

    const int n_out4 = N * 16;                  // out as float4
    const int n_dc4  = (N * 2 + 3) / 4;         // dencnt as float4
    zero_kernel<<<(n_out4 + 255) / 256, 256>>>((float4*)out, (const float4*)ego,
                                               Wg, n_out4, n_dc4);

    const int tiles = (N + 127) / 128;
    gemm_transform<<<tiles * 16, 256, SMEM_SZ>>>(N);

    // 8 edges per warp, 64 per CTA
    edge_pass<<<(E + 63) / 64, 256>>>(heads, tails, et, out, N, E);

    pass3_mean<<<(n_out4 + 255) / 256, 256>>>((float4*)out, N);
}

// round 11
// speedup vs baseline: 1.8653x; 1.1610x over previous
#include <cuda_runtime.h>
#include <cuda_bf16.h>
#include <cuda_fp16.h>
#include <math.h>
#include <stdint.h>

// ---------------------------------------------------------------------------
// Aggregator: relational graph attention, tensor-core (warp mma.sync) version.
//   Y[r]     = ego @ W[r]            (bf16 HMMA, fp32 accumulate, fp16 store)
//   s_e      = leaky_relu( Y[et_e, h_e] . ego[t_e] )
//   out[n]   = sum_e exp(s_e) * ego[t_e]  /  ( den[n] * max(cnt[n],1) )
// GEMM: serial 16-relation loop per 128-row tile; Y stores staged through
// smem so global writes are full coalesced 128B lines.
// ---------------------------------------------------------------------------

#define N_CAP   131072
#define YROWS   102400               // >= N, multiple of 128
__device__ __half g_Yh[16u * YROWS * 64u];     // [R, N, 64] fp16
__device__ __half g_egoh[(size_t)N_CAP * 64];  // [N, 64] fp16 mirror of ego
__device__ float2 g_dencnt[N_CAP];             // (den, cnt) per head node

// pre-transposed W (row n, col k), padded row stride AS, bf16
#define AS 72
__device__ __nv_bfloat16 g_Wt[16 * 64 * AS];

__device__ __forceinline__ uint32_t smem_u32(const void* p) {
    uint32_t a;
    asm("{ .reg .u64 t; cvta.to.shared.u64 t, %1; cvt.u32.u64 %0, t; }"
        : "=r"(a) : "l"(p));
    return a;
}
__device__ __forceinline__ void ldm_x4(uint32_t* r, uint32_t addr) {
    asm volatile("ldmatrix.sync.aligned.m8n8.x4.shared.b16 {%0,%1,%2,%3}, [%4];"
                 : "=r"(r[0]), "=r"(r[1]), "=r"(r[2]), "=r"(r[3]) : "r"(addr));
}
__device__ __forceinline__ void mma_bf16(float* c, const uint32_t* a,
                                         uint32_t b0, uint32_t b1) {
    asm volatile(
        "mma.sync.aligned.m16n8k16.row.col.f32.bf16.bf16.f32 "
        "{%0,%1,%2,%3}, {%4,%5,%6,%7}, {%8,%9}, {%0,%1,%2,%3};"
        : "+f"(c[0]), "+f"(c[1]), "+f"(c[2]), "+f"(c[3])
        : "r"(a[0]), "r"(a[1]), "r"(a[2]), "r"(a[3]), "r"(b0), "r"(b1));
}
__device__ __forceinline__ uint32_t pack2(float x0, float x1) {
    return ((uint32_t)__bfloat16_as_ushort(__float2bfloat16(x1)) << 16)
         | (uint32_t)__bfloat16_as_ushort(__float2bfloat16(x0));
}

// smem layout (bytes): region0 = A tile, later reused as Y staging
//   (128 rows x AS halves = 18432B); region1 = B tile (9216B)
#define A_OFF   0
#define B_OFF   18432
#define SMEM_SZ (18432 + 9216 + 128)

// ============================ kernels ======================================

// ---- zero out + dencnt + fp16 ego mirror; blocks 0..15 also prep W --------
__global__ void zero_kernel(float4* __restrict__ out4,
                            const float4* __restrict__ ego4,
                            const float* __restrict__ Wg,
                            int n_out4, int n_dc4)
{
    int i = blockIdx.x * blockDim.x + threadIdx.x;
    if (i < n_out4) {
        out4[i] = make_float4(0.f, 0.f, 0.f, 0.f);
        float4 v = ego4[i];
        __half2 h0 = __floats2half2_rn(v.x, v.y);
        __half2 h1 = __floats2half2_rn(v.z, v.w);
        *(uint2*)(g_egoh + (size_t)i * 4) =
            make_uint2(*(uint32_t*)&h0, *(uint32_t*)&h1);
    }
    if (i < n_dc4) ((float4*)g_dencnt)[i] = make_float4(0.f, 0.f, 0.f, 0.f);

    if (blockIdx.x < 16) {           // W transpose to bf16, padded stride
        const int r = blockIdx.x;
        for (int idx = threadIdx.x; idx < 4096; idx += 256) {
            int k = idx >> 6, n = idx & 63;          // W[k][n], coalesced read
            float v = Wg[(size_t)r * 4096 + idx];
            g_Wt[r * 64 * AS + n * AS + k] = __float2bfloat16(v);
        }
    }
}

// ---- GEMM: Y[r] = X @ W[r]; 128-row tile per CTA, smem-staged stores ------
__global__ __launch_bounds__(256) void gemm_transform(
    const float* __restrict__ ego, int N)
{
    extern __shared__ __align__(16) char sm[];
    __nv_bfloat16* sh = (__nv_bfloat16*)sm;
    __half* stag = (__half*)sm;                  // staging aliases A region
    const uint32_t smb = smem_u32(sm);

    const int tid  = threadIdx.x;
    const int wid  = tid >> 5;
    const int lane = tid & 31;
    const int tile = blockIdx.x;
    const int rows = min(128, N - tile * 128);

    // --- stage A tile (ego rows) as bf16, zero-padded ----------------------
    for (int i = tid * 2; i < 128 * 64; i += 512) {
        int row = i >> 6, col = i & 63;
        float v0 = 0.f, v1 = 0.f;
        if (row < rows) {
            const float2 v = *(const float2*)(ego + ((size_t)(tile * 128 + row)) * 64 + col);
            v0 = v.x; v1 = v.y;
        }
        *(uint32_t*)(sh + row * AS + col) = pack2(v0, v1);
    }
    __syncthreads();

    // --- per-warp A fragment: 16 rows x K=64, held in registers ------------
    const int m0   = wid * 16;
    const int frow = (lane & 7) + ((lane >> 3) & 1) * 8;
    const int fcol = (lane >> 4) * 8;
    uint32_t Af[4][4];
    #pragma unroll
    for (int kt = 0; kt < 4; kt++) {
        uint32_t off = (uint32_t)((m0 + frow) * AS + kt * 16 + fcol) * 2;
        ldm_x4(Af[kt], smb + A_OFF + off);
    }

    const int g  = lane >> 2;         // output row within 8-group
    const int tq = lane & 3;          // output col pair

    for (int r = 0; r < 16; r++) {
        // stage B = pre-transposed W_r (pure vector copies)
        {
            const uint4* src = (const uint4*)(g_Wt + r * 64 * AS);
            uint4* dst = (uint4*)(sm + B_OFF);
            #pragma unroll
            for (int k = 0; k < 3; k++) {
                int i = tid + k * 256;
                if (i < 576) dst[i] = src[i];
            }
        }
        __syncthreads();   // B staged; also: all warps done reading staging (r>0)
                           // and done with Af loads from A region (r==0)

        float acc[8][4];
        #pragma unroll
        for (int i = 0; i < 8; i++)
            #pragma unroll
            for (int j = 0; j < 4; j++) acc[i][j] = 0.f;

        #pragma unroll
        for (int nt = 0; nt < 4; nt++) {
            #pragma unroll
            for (int kt = 0; kt < 4; kt++) {
                uint32_t boff = (uint32_t)((nt * 16 + frow) * AS + kt * 16 + fcol) * 2;
                uint32_t Bf[4];
                ldm_x4(Bf, smb + B_OFF + boff);
                mma_bf16(acc[2 * nt],     Af[kt], Bf[0], Bf[2]);
                mma_bf16(acc[2 * nt + 1], Af[kt], Bf[1], Bf[3]);
            }
        }

        // --- STS fragments to staging (padded stride AS -> no row aliasing)
        {
            int row0 = m0 + g;
            #pragma unroll
            for (int nt8 = 0; nt8 < 8; nt8++) {
                int col = nt8 * 8 + tq * 2;
                __half2 ha = __floats2half2_rn(acc[nt8][0], acc[nt8][1]);
                __half2 hb = __floats2half2_rn(acc[nt8][2], acc[nt8][3]);
                *(__half2*)(stag + row0 * AS + col)       = ha;
                *(__half2*)(stag + (row0 + 8) * AS + col) = hb;
            }
        }
        __syncthreads();

        // --- coalesced Y writeback: full 128B lines ------------------------
        {
            uint32_t ybase = ((uint32_t)r * (uint32_t)N + (uint32_t)(tile * 128)) * 64u;
            #pragma unroll
            for (int q = 0; q < 4; q++) {
                int i = tid + q * 256;            // 1024 uint4 total
                int row = i >> 3, seg = i & 7;
                if (row < rows) {
                    uint4 v = *(const uint4*)(stag + row * AS + seg * 8);
                    *(uint4*)(g_Yh + ybase + (uint32_t)row * 64u + seg * 8) = v;
                }
            }
        }
        // next iteration's post-B-stage barrier orders staging reuse
    }
}

// ---- fused edge pass: 8 edges/warp (4 per half), fp16 gathers -------------
__global__ __launch_bounds__(256) void edge_pass(
    const int*   __restrict__ heads,
    const int*   __restrict__ tails,
    const int*   __restrict__ etype,
    float*       __restrict__ out,
    int N, int E)
{
    const int warp = (blockIdx.x * 256 + threadIdx.x) >> 5;
    const int lane = threadIdx.x & 31;
    const int half = lane >> 4;
    const int l2   = lane & 15;
    const unsigned hmask = 0xFFFFu << (half * 16);

    const int ebase = warp * 8 + half * 4;     // this half-warp: 4 edges
    if (ebase >= E) return;

    int4 hh, tt, rr;
    if (ebase + 3 < E) {
        hh = *(const int4*)(heads + ebase);
        tt = *(const int4*)(tails + ebase);
        rr = *(const int4*)(etype + ebase);
    } else {
        int* hp = (int*)&hh; int* tp = (int*)&tt; int* rp = (int*)&rr;
        #pragma unroll
        for (int j = 0; j < 4; j++) {
            int e = min(ebase + j, E - 1);
            hp[j] = heads[e]; tp[j] = tails[e]; rp[j] = etype[e];
        }
    }
    const int* hp = (const int*)&hh;
    const int* tp = (const int*)&tt;
    const int* rp = (const int*)&rr;

    const uint32_t c8 = (uint32_t)(l2 * 4);

    // issue all gathers first (8 independent loads in flight)
    uint2 yv[4], tv[4];
    #pragma unroll
    for (int j = 0; j < 4; j++) {
        yv[j] = *(const uint2*)(g_Yh + ((uint32_t)rp[j] * (uint32_t)N + (uint32_t)hp[j]) * 64u + c8);
        tv[j] = *(const uint2*)(g_egoh + (uint32_t)tp[j] * 64u + c8);
    }

    float p[4];
    float tf[4][4];
    #pragma unroll
    for (int j = 0; j < 4; j++) {
        float2 ya = __half22float2(*(__half2*)&yv[j].x);
        float2 yb = __half22float2(*(__half2*)&yv[j].y);
        float2 ta = __half22float2(*(__half2*)&tv[j].x);
        float2 tb = __half22float2(*(__half2*)&tv[j].y);
        tf[j][0] = ta.x; tf[j][1] = ta.y; tf[j][2] = tb.x; tf[j][3] = tb.y;
        p[j] = ya.x * ta.x + ya.y * ta.y + yb.x * tb.x + yb.y * tb.y;
    }
    #pragma unroll
    for (int o = 1; o < 16; o <<= 1) {
        #pragma unroll
        for (int j = 0; j < 4; j++)
            p[j] += __shfl_xor_sync(hmask, p[j], o);
    }

    float ex[4];
    #pragma unroll
    for (int j = 0; j < 4; j++) {
        float s = p[j] > 0.f ? p[j] : 0.01f * p[j];
        ex[j] = __expf(s);
    }

    #pragma unroll
    for (int j = 0; j < 4; j++) {
        if (ebase + j >= E) break;
        if (l2 == 0)
            asm volatile("red.global.add.v2.f32 [%0], {%1, %2};"
                         :: "l"(&g_dencnt[hp[j]]), "f"(ex[j]), "f"(1.0f) : "memory");
        float* op = out + (uint32_t)hp[j] * 64u + c8;
        asm volatile("red.global.add.v4.f32 [%0], {%1, %2, %3, %4};"
                     :: "l"(op), "f"(ex[j] * tf[j][0]), "f"(ex[j] * tf[j][1]),
                        "f"(ex[j] * tf[j][2]), "f"(ex[j] * tf[j][3]) : "memory");
    }
}

// ---- epilogue: divide by den * max(cnt,1), float4 per thread --------------
__global__ void pass3_mean(float4* __restrict__ out4, int N)
{
    int i = blockIdx.x * blockDim.x + threadIdx.x;    // one float4 (4 elems)
    if (i < N * 16) {
        float2 dc = g_dencnt[i >> 4];
        float s = (dc.y > 0.0f) ? __frcp_rn(dc.x * dc.y) : 0.0f;
        float4 v = out4[i];
        v.x *= s; v.y *= s; v.z *= s; v.w *= s;
        out4[i] = v;
    }
}

// ---------------------------------------------------------------------------
extern "C" void kernel_launch(void* const* d_in, const int* in_sizes, int n_in,
                              void* d_out, int out_size)
{
    const float* ego = (const float*)d_in[0];   // [N,64] f32
    const float* Wg  = (const float*)d_in[1];   // [16,64,64] f32
    const int*   ei  = (const int*)d_in[2];     // [2,E] i32
    const int*   et  = (const int*)d_in[3];     // [E] i32
    float* out = (float*)d_out;

    const int N = in_sizes[0] / 64;
    const int E = in_sizes[3];
    const int* heads = ei;
    const int* tails = ei + E;

    cudaFuncSetAttribute(gemm_transform,
                         cudaFuncAttributeMaxDynamicSharedMemorySize, SMEM_SZ);

    const int n_out4 = N * 16;                  // out as float4
    const int n_dc4  = (N * 2 + 3) / 4;         // dencnt as float4
    zero_kernel<<<(n_out4 + 255) / 256, 256>>>((float4*)out, (const float4*)ego,
                                               Wg, n_out4, n_dc4);

    const int tiles = (N + 127) / 128;
    gemm_transform<<<tiles, 256, SMEM_SZ>>>(ego, N);

    // 8 edges per warp, 64 per CTA
    edge_pass<<<(E + 63) / 64, 256>>>(heads, tails, et, out, N, E);

    pass3_mean<<<(n_out4 + 255) / 256, 256>>>((float4*)out, N);
}